// round 10
// baseline (speedup 1.0000x reference)
#include <cuda_runtime.h>
#include <cuda_bf16.h>

// GAE backward affine suffix scan. Inputs: rewards f32 [B,S], values f32 [B,S],
// dones i32 [B,S], mask i32 [B,S] (PREFIX mask 1...1 0...0 per row).
// Output: [advantages; returns], 2*B*S floats.
//
//   L     = prefix length;  valid[t] = t < L
//   nd    = 1 - done
//   delta = r + GAMMA * values[t+1]*valid[t+1] * nd - v
//   g[t]  = valid[t] ? (delta + GAMMA*LAMBDA*nd * g[t+1]) : 0
//   adv = g ; ret = valid ? g + v : 0
//
// Mask traffic (~64 MiB) replaced by:
//  kernel 1 (w0_kernel): one warp/row, 32 probes at stride 64, one ballot ->
//    64-aligned window base w0 with w0 < L <= w0+64 (single load round).
//  kernel 2 (gae_kernel): w0 is known at entry, so warp 0 fetches the whole
//    64-word boundary window with ONE coalesced 256B load into smem (front
//    batch, no dependent rounds). Chunks below the window are provably valid,
//    above provably invalid; only window chunks consult smem.

#define GAMMA  0.999f
#define LAMBDA 0.95f
#define GL     (GAMMA * LAMBDA)
#define S_LEN  2048
#define TPB    256
#define EPT    8           // TPB*EPT == S_LEN
#define NW     (TPB / 32)  // 8 warps
#define MAX_B  8192

__device__ int g_w0[MAX_B];

__global__ __launch_bounds__(256)
void w0_kernel(const int* __restrict__ mask, int B)
{
    const int gw   = (blockIdx.x * 256 + threadIdx.x) >> 5;   // warp id = row
    const int lane = threadIdx.x & 31;
    if (gw >= B) return;

    // mask[64*lane] = 1 iff 64*lane < L (prefix mask).
    int p = __ldg(mask + (long long)gw * S_LEN + lane * 64);
    unsigned b = __ballot_sync(0xffffffffu, p != 0);
    if (lane == 0)
        g_w0[gw] = (b == 0u) ? -64 : (int)(__popc(b) - 1) * 64;  // w0 < L <= w0+64
}

__global__ __launch_bounds__(TPB)
void gae_kernel(const float* __restrict__ rewards,
                const float* __restrict__ values,
                const int*   __restrict__ dones,
                const int*   __restrict__ mask,
                float* __restrict__ adv_out,
                float* __restrict__ ret_out)
{
    const int tid  = threadIdx.x;
    const unsigned lane = tid & 31u;
    const unsigned warp = tid >> 5;

    const long long rowbase = (long long)blockIdx.x * S_LEN;
    const long long base    = rowbase + tid * EPT;
    const int t0 = tid * EPT;

    // Scalar window base (written by kernel 1; L2-resident 32KB table).
    const int w0 = __ldg(&g_w0[blockIdx.x]);

    // Coalesced streaming vector loads (touch-once -> evict-first).
    const float4* rp = reinterpret_cast<const float4*>(rewards + base);
    const float4* vp = reinterpret_cast<const float4*>(values  + base);
    const int4*   dp = reinterpret_cast<const int4*>(dones + base);
    float4 r4a = __ldcs(rp);     float4 r4b = __ldcs(rp + 1);
    float4 v4a = __ldcs(vp);     float4 v4b = __ldcs(vp + 1);
    int4   d4a = __ldcs(dp);     int4   d4b = __ldcs(dp + 1);

    // Warp 0: one coalesced 256B load of the boundary window into smem.
    __shared__ __align__(16) int smask[68];   // [64] = 0 sentinel
    if (warp == 0) {
        if (lane < 16 && w0 >= 0) {
            int4 m = __ldg(reinterpret_cast<const int4*>(mask + rowbase + w0) + lane);
            reinterpret_cast<int4*>(smask)[lane] = m;
        }
        if (lane == 16) smask[64] = 0;
    }

    // Neighbor (t+1) value exchange (same sync publishes smask).
    __shared__ float nbr[TPB];
    nbr[tid] = v4a.x;
    __syncthreads();
    float v_next = (tid + 1 < TPB) ? nbr[tid + 1] : 0.f;

    // Per-element validity from w0 (+ smem window for boundary chunks).
    float mk[EPT], mn[EPT];
    if (t0 >= w0 && t0 < w0 + 64) {
        const int o = t0 - w0;                    // 0,8,...,56
#pragma unroll
        for (int j = 0; j < EPT; ++j) {
            mk[j] = (float)smask[o + j];
            mn[j] = (float)smask[o + j + 1];      // [64] sentinel = 0
        }
    } else {
        const float all = (t0 < w0) ? 1.f : 0.f;  // below: w0 < L -> valid
#pragma unroll
        for (int j = 0; j < EPT; ++j) { mk[j] = all; mn[j] = all; }
        // Below-window j=7: t+1 = t0+8 <= w0 < L -> mn=1 correct.
    }

    float r[EPT]  = {r4a.x, r4a.y, r4a.z, r4a.w, r4b.x, r4b.y, r4b.z, r4b.w};
    float v[EPT]  = {v4a.x, v4a.y, v4a.z, v4a.w, v4b.x, v4b.y, v4b.z, v4b.w};
    float nd[EPT] = {1.f - (float)d4a.x, 1.f - (float)d4a.y,
                     1.f - (float)d4a.z, 1.f - (float)d4a.w,
                     1.f - (float)d4b.x, 1.f - (float)d4b.y,
                     1.f - (float)d4b.z, 1.f - (float)d4b.w};
    float nv[EPT] = {v[1], v[2], v[3], v[4], v[5], v[6], v[7], v_next};

    // Per-element affine transforms (c, d); invalid steps -> (0, 0).
    float c[EPT], d[EPT];
#pragma unroll
    for (int j = 0; j < EPT; ++j) {
        float nvj   = nv[j] * mn[j];
        float delta = fmaf(GAMMA * nd[j], nvj, r[j]) - v[j];
        c[j] = mk[j] * GL * nd[j];
        d[j] = mk[j] * delta;
    }

    // Thread-local composition over the 8 steps (reverse time order).
    float A = 1.f, Bc = 0.f;
#pragma unroll
    for (int j = EPT - 1; j >= 0; --j) {
        Bc = fmaf(c[j], Bc, d[j]);
        A  = c[j] * A;
    }

    // Warp-level inclusive suffix scan (Kogge-Stone, shfl_down).
    float a = A, b = Bc;
#pragma unroll
    for (int off = 1; off < 32; off <<= 1) {
        float ra = __shfl_down_sync(0xffffffffu, a, off);
        float rb = __shfl_down_sync(0xffffffffu, b, off);
        if (lane + off < 32) {
            b = fmaf(a, rb, b);
            a = a * ra;
        }
    }
    // Exclusive suffix within warp: E_i = inclusive(i+1); identity at lane 31.
    float ea = __shfl_down_sync(0xffffffffu, a, 1);
    float eb = __shfl_down_sync(0xffffffffu, b, 1);
    if (lane == 31) { ea = 1.f; eb = 0.f; }

    // Cross-warp scan over NW=8 warp aggregates.
    __shared__ float wa[NW];
    __shared__ float wb[NW];
    __shared__ float wcarry[NW];
    if (lane == 0) { wa[warp] = a; wb[warp] = b; }
    __syncthreads();
    if (warp == 0 && lane < NW) {
        float aa = wa[lane], bb = wb[lane];
#pragma unroll
        for (int off = 1; off < NW; off <<= 1) {
            float ra = __shfl_down_sync(0x000000ffu, aa, off);
            float rb = __shfl_down_sync(0x000000ffu, bb, off);
            if (lane + off < NW) {
                bb = fmaf(aa, rb, bb);
                aa = aa * ra;
            }
        }
        float carry = __shfl_down_sync(0x000000ffu, bb, 1);
        if (lane == NW - 1) carry = 0.f;
        wcarry[lane] = carry;
    }
    __syncthreads();

    // Carry entering this thread's chunk from the right, then final pass.
    float g = fmaf(ea, wcarry[warp], eb);

    float adv[EPT], ret[EPT];
#pragma unroll
    for (int j = EPT - 1; j >= 0; --j) {
        g = fmaf(c[j], g, d[j]);   // exactly 0 where invalid (c=d=0)
        adv[j] = g;
        ret[j] = (mk[j] != 0.f) ? (g + v[j]) : 0.f;
    }

    float4* ap = reinterpret_cast<float4*>(adv_out + base);
    float4* tp = reinterpret_cast<float4*>(ret_out + base);
    __stcs(ap,     make_float4(adv[0], adv[1], adv[2], adv[3]));
    __stcs(ap + 1, make_float4(adv[4], adv[5], adv[6], adv[7]));
    __stcs(tp,     make_float4(ret[0], ret[1], ret[2], ret[3]));
    __stcs(tp + 1, make_float4(ret[4], ret[5], ret[6], ret[7]));
}

extern "C" void kernel_launch(void* const* d_in, const int* in_sizes, int n_in,
                              void* d_out, int out_size)
{
    const float* rewards = (const float*)d_in[0];
    const float* values  = (const float*)d_in[1];
    const int*   dones   = (const int*)d_in[2];
    const int*   mask    = (const int*)d_in[3];

    const int total = in_sizes[0];            // B * S
    const int B     = total / S_LEN;

    float* adv_out = (float*)d_out;
    float* ret_out = (float*)d_out + (long long)B * S_LEN;

    // Kernel 1: per-row window base (one warp per row, one load round).
    const int lb = 256;
    const int lg = (B * 32 + lb - 1) / lb;
    w0_kernel<<<lg, lb>>>(mask, B);

    // Kernel 2: streaming GAE scan; boundary window resolved from smem.
    gae_kernel<<<B, TPB>>>(rewards, values, dones, mask, adv_out, ret_out);
}

// round 11
// speedup vs baseline: 1.0956x; 1.0956x over previous
#include <cuda_runtime.h>
#include <cuda_bf16.h>

// GAE backward affine suffix scan. Inputs: rewards f32 [B,S], values f32 [B,S],
// dones i32 [B,S], mask i32 [B,S] (PREFIX mask 1...1 0...0 per row).
// Output: [advantages; returns], 2*B*S floats.
//
//   L     = prefix length;  valid[t] = t < L
//   nd    = 1 - done
//   delta = r + GAMMA * values[t+1]*[t+1<L] * nd - v
//   g[t]  = [t<L] ? (delta + GAMMA*LAMBDA*nd * g[t+1]) : 0
//   adv = g ; ret = [t<L] ? g + v : 0
//
// kernel 1 (len_kernel): one warp/row, exact L via 2-round boundary search
//   (32 stride-64 probes + 64-word window refinement). ~10 MB traffic.
// kernel 2 (gae_kernel): mask-free streaming scan using t < L compares.
//   NEW: threads whose whole chunk is invalid (t0 >= ceil8(L)) skip their
//   r/v/d loads entirely (mean 25% of reads eliminated; outputs there are
//   exactly zero, which we still write since d_out is poisoned).

#define GAMMA  0.999f
#define LAMBDA 0.95f
#define GL     (GAMMA * LAMBDA)
#define S_LEN  2048
#define TPB    256
#define EPT    8           // TPB*EPT == S_LEN
#define NW     (TPB / 32)  // 8 warps
#define MAX_B  8192

__device__ int g_L[MAX_B];

__global__ __launch_bounds__(256)
void len_kernel(const int* __restrict__ mask, int B)
{
    const int gw   = (blockIdx.x * 256 + threadIdx.x) >> 5;   // warp id = row
    const int lane = threadIdx.x & 31;
    if (gw >= B) return;

    const int* mrow = mask + (long long)gw * S_LEN;

    // Round 1: 32 probes at stride 64. mask[64*lane]=1 iff 64*lane < L.
    int p1 = __ldg(mrow + lane * 64);
    unsigned b1 = __ballot_sync(0xffffffffu, p1 != 0);

    int L = 0;
    if (b1 != 0u) {
        int k  = __popc(b1);          // L in (64(k-1), 64k]
        int w0 = (k - 1) * 64;
        // Round 2: 64 contiguous probes (2 per lane) in the window.
        int q0 = __ldg(mrow + w0 + 2 * lane);
        int q1 = __ldg(mrow + w0 + 2 * lane + 1);
        unsigned c0 = __ballot_sync(0xffffffffu, q0 != 0);
        unsigned c1 = __ballot_sync(0xffffffffu, q1 != 0);
        L = w0 + __popc(c0) + __popc(c1);
    }
    if (lane == 0) g_L[gw] = L;
}

__global__ __launch_bounds__(TPB)
void gae_kernel(const float* __restrict__ rewards,
                const float* __restrict__ values,
                const int*   __restrict__ dones,
                float* __restrict__ adv_out,
                float* __restrict__ ret_out)
{
    const int tid  = threadIdx.x;
    const unsigned lane = tid & 31u;
    const unsigned warp = tid >> 5;

    const long long base = (long long)blockIdx.x * S_LEN + tid * EPT;
    const int t0 = tid * EPT;

    // Valid prefix length for this row (tiny L2-resident table).
    const int L = __ldg(&g_L[blockIdx.x]);

    // Load only if this chunk intersects the valid prefix; fully-invalid
    // chunks contribute the absorbing (0,0) transform and write zeros, so
    // their inputs are never needed (saves ~25% of read traffic on average).
    const bool doLoad = (t0 < L);

    float4 r4a = make_float4(0.f,0.f,0.f,0.f), r4b = r4a;
    float4 v4a = r4a, v4b = r4a;
    int4   d4a = make_int4(0,0,0,0), d4b = d4a;
    if (doLoad) {
        const float4* rp = reinterpret_cast<const float4*>(rewards + base);
        const float4* vp = reinterpret_cast<const float4*>(values  + base);
        const int4*   dp = reinterpret_cast<const int4*>(dones + base);
        r4a = __ldcs(rp);     r4b = __ldcs(rp + 1);
        v4a = __ldcs(vp);     v4b = __ldcs(vp + 1);
        d4a = __ldcs(dp);     d4b = __ldcs(dp + 1);
    }

    // Neighbor (t+1) value exchange (zero for non-loading threads; any use
    // of it is gated by t+1 < L which is false there).
    __shared__ float nbr[TPB];
    nbr[tid] = v4a.x;
    __syncthreads();
    float v_next = (tid + 1 < TPB) ? nbr[tid + 1] : 0.f;

    float r[EPT]  = {r4a.x, r4a.y, r4a.z, r4a.w, r4b.x, r4b.y, r4b.z, r4b.w};
    float v[EPT]  = {v4a.x, v4a.y, v4a.z, v4a.w, v4b.x, v4b.y, v4b.z, v4b.w};
    float nd[EPT] = {1.f - (float)d4a.x, 1.f - (float)d4a.y,
                     1.f - (float)d4a.z, 1.f - (float)d4a.w,
                     1.f - (float)d4b.x, 1.f - (float)d4b.y,
                     1.f - (float)d4b.z, 1.f - (float)d4b.w};
    float nv[EPT] = {v[1], v[2], v[3], v[4], v[5], v[6], v[7], v_next};

    // Per-element affine transforms (c, d); invalid steps -> (0, 0).
    float c[EPT], d[EPT], mk[EPT];
#pragma unroll
    for (int j = 0; j < EPT; ++j) {
        float m  = (t0 + j     < L) ? 1.f : 0.f;
        float mn = (t0 + j + 1 < L) ? 1.f : 0.f;
        float nvj   = nv[j] * mn;
        float delta = fmaf(GAMMA * nd[j], nvj, r[j]) - v[j];
        c[j]  = m * GL * nd[j];
        d[j]  = m * delta;
        mk[j] = m;
    }

    // Thread-local composition over the 8 steps (reverse time order).
    float A = 1.f, Bc = 0.f;
#pragma unroll
    for (int j = EPT - 1; j >= 0; --j) {
        Bc = fmaf(c[j], Bc, d[j]);
        A  = c[j] * A;
    }

    // Warp-level inclusive suffix scan (Kogge-Stone, shfl_down).
    float a = A, b = Bc;
#pragma unroll
    for (int off = 1; off < 32; off <<= 1) {
        float ra = __shfl_down_sync(0xffffffffu, a, off);
        float rb = __shfl_down_sync(0xffffffffu, b, off);
        if (lane + off < 32) {
            b = fmaf(a, rb, b);
            a = a * ra;
        }
    }
    // Exclusive suffix within warp: E_i = inclusive(i+1); identity at lane 31.
    float ea = __shfl_down_sync(0xffffffffu, a, 1);
    float eb = __shfl_down_sync(0xffffffffu, b, 1);
    if (lane == 31) { ea = 1.f; eb = 0.f; }

    // Cross-warp scan over NW=8 warp aggregates.
    __shared__ float wa[NW];
    __shared__ float wb[NW];
    __shared__ float wcarry[NW];
    if (lane == 0) { wa[warp] = a; wb[warp] = b; }
    __syncthreads();
    if (warp == 0 && lane < NW) {
        float aa = wa[lane], bb = wb[lane];
#pragma unroll
        for (int off = 1; off < NW; off <<= 1) {
            float ra = __shfl_down_sync(0x000000ffu, aa, off);
            float rb = __shfl_down_sync(0x000000ffu, bb, off);
            if (lane + off < NW) {
                bb = fmaf(aa, rb, bb);
                aa = aa * ra;
            }
        }
        float carry = __shfl_down_sync(0x000000ffu, bb, 1);
        if (lane == NW - 1) carry = 0.f;
        wcarry[lane] = carry;
    }
    __syncthreads();

    // Carry entering this thread's chunk from the right, then final pass.
    float g = fmaf(ea, wcarry[warp], eb);

    float adv[EPT], ret[EPT];
#pragma unroll
    for (int j = EPT - 1; j >= 0; --j) {
        g = fmaf(c[j], g, d[j]);   // exactly 0 where invalid (c=d=0)
        adv[j] = g;
        ret[j] = (mk[j] != 0.f) ? (g + v[j]) : 0.f;
    }

    float4* ap = reinterpret_cast<float4*>(adv_out + base);
    float4* tp = reinterpret_cast<float4*>(ret_out + base);
    __stcs(ap,     make_float4(adv[0], adv[1], adv[2], adv[3]));
    __stcs(ap + 1, make_float4(adv[4], adv[5], adv[6], adv[7]));
    __stcs(tp,     make_float4(ret[0], ret[1], ret[2], ret[3]));
    __stcs(tp + 1, make_float4(ret[4], ret[5], ret[6], ret[7]));
}

extern "C" void kernel_launch(void* const* d_in, const int* in_sizes, int n_in,
                              void* d_out, int out_size)
{
    const float* rewards = (const float*)d_in[0];
    const float* values  = (const float*)d_in[1];
    const int*   dones   = (const int*)d_in[2];
    const int*   mask    = (const int*)d_in[3];

    const int total = in_sizes[0];            // B * S
    const int B     = total / S_LEN;

    float* adv_out = (float*)d_out;
    float* ret_out = (float*)d_out + (long long)B * S_LEN;

    // Kernel 1: exact per-row prefix lengths (one warp per row).
    const int lb = 256;
    const int lg = (B * 32 + lb - 1) / lb;
    len_kernel<<<lg, lb>>>(mask, B);

    // Kernel 2: streaming GAE scan; invalid-tail chunks skip input loads.
    gae_kernel<<<B, TPB>>>(rewards, values, dones, adv_out, ret_out);
}

// round 12
// speedup vs baseline: 1.1328x; 1.0339x over previous
#include <cuda_runtime.h>
#include <cuda_bf16.h>

// GAE backward affine suffix scan. Inputs: rewards f32 [B,S], values f32 [B,S],
// dones i32 [B,S], mask i32 [B,S] (PREFIX mask 1...1 0...0 per row).
// Output: [advantages; returns], 2*B*S floats.
//
//   L     = prefix length;  valid[t] = t < L
//   nd    = 1 - done
//   delta = r + GAMMA * values[t+1]*[t+1<L] * nd - v
//   g[t]  = [t<L] ? (delta + GAMMA*LAMBDA*nd * g[t+1]) : 0
//   adv = g ; ret = [t<L] ? g + v : 0   (== g + mk*v since g=0 where invalid)
//
// kernel 1 (len_kernel): one warp/row, exact L via 2-round boundary search.
// kernel 2 (gae_kernel): TPB=128 x EPT=16 streaming scan (4 warps/CTA ->
//   half the shuffle/barrier overhead of the 256x8 version); fully-invalid
//   chunks skip their input loads (outputs exactly zero, still written).

#define GAMMA  0.999f
#define LAMBDA 0.95f
#define GL     (GAMMA * LAMBDA)
#define S_LEN  2048
#define TPB    128
#define EPT    16          // TPB*EPT == S_LEN
#define NSEG   (EPT / 4)   // 4 float4 segments per array
#define NW     (TPB / 32)  // 4 warps
#define MAX_B  8192

__device__ int g_L[MAX_B];

__global__ __launch_bounds__(256)
void len_kernel(const int* __restrict__ mask, int B)
{
    const int gw   = (blockIdx.x * 256 + threadIdx.x) >> 5;   // warp id = row
    const int lane = threadIdx.x & 31;
    if (gw >= B) return;

    const int* mrow = mask + (long long)gw * S_LEN;

    // Round 1: 32 probes at stride 64. mask[64*lane]=1 iff 64*lane < L.
    int p1 = __ldg(mrow + lane * 64);
    unsigned b1 = __ballot_sync(0xffffffffu, p1 != 0);

    int L = 0;
    if (b1 != 0u) {
        int k  = __popc(b1);          // L in (64(k-1), 64k]
        int w0 = (k - 1) * 64;
        // Round 2: 64 contiguous probes (2 per lane) in the window.
        int q0 = __ldg(mrow + w0 + 2 * lane);
        int q1 = __ldg(mrow + w0 + 2 * lane + 1);
        unsigned c0 = __ballot_sync(0xffffffffu, q0 != 0);
        unsigned c1 = __ballot_sync(0xffffffffu, q1 != 0);
        L = w0 + __popc(c0) + __popc(c1);
    }
    if (lane == 0) g_L[gw] = L;
}

__global__ __launch_bounds__(TPB)
void gae_kernel(const float* __restrict__ rewards,
                const float* __restrict__ values,
                const int*   __restrict__ dones,
                float* __restrict__ adv_out,
                float* __restrict__ ret_out)
{
    const int tid  = threadIdx.x;
    const unsigned lane = tid & 31u;
    const unsigned warp = tid >> 5;

    const long long base = (long long)blockIdx.x * S_LEN + tid * EPT;
    const int t0 = tid * EPT;

    // Valid prefix length for this row (tiny L2-resident table).
    const int L = __ldg(&g_L[blockIdx.x]);

    // Front-batched loads; fully-invalid chunks skip (outputs are zeros).
    const bool doLoad = (t0 < L);

    float4 R[NSEG], V[NSEG];
    int4   D[NSEG];
#pragma unroll
    for (int i = 0; i < NSEG; ++i) {
        R[i] = make_float4(0.f, 0.f, 0.f, 0.f);
        V[i] = R[i];
        D[i] = make_int4(0, 0, 0, 0);
    }
    if (doLoad) {
        const float4* rp = reinterpret_cast<const float4*>(rewards + base);
        const float4* vp = reinterpret_cast<const float4*>(values  + base);
        const int4*   dp = reinterpret_cast<const int4*>(dones + base);
#pragma unroll
        for (int i = 0; i < NSEG; ++i) R[i] = __ldcs(rp + i);
#pragma unroll
        for (int i = 0; i < NSEG; ++i) V[i] = __ldcs(vp + i);
#pragma unroll
        for (int i = 0; i < NSEG; ++i) D[i] = __ldcs(dp + i);
    }

    // Neighbor (t+1) value exchange (zero for non-loading threads; any use
    // is gated by t+1 < L, false there).
    __shared__ float nbr[TPB];
    nbr[tid] = V[0].x;
    __syncthreads();
    const float v_next = (tid + 1 < TPB) ? nbr[tid + 1] : 0.f;

    float r[EPT], v[EPT], nd[EPT];
#pragma unroll
    for (int i = 0; i < NSEG; ++i) {
        r[4*i+0] = R[i].x;  r[4*i+1] = R[i].y;  r[4*i+2] = R[i].z;  r[4*i+3] = R[i].w;
        v[4*i+0] = V[i].x;  v[4*i+1] = V[i].y;  v[4*i+2] = V[i].z;  v[4*i+3] = V[i].w;
        nd[4*i+0] = 1.f - (float)D[i].x;  nd[4*i+1] = 1.f - (float)D[i].y;
        nd[4*i+2] = 1.f - (float)D[i].z;  nd[4*i+3] = 1.f - (float)D[i].w;
    }

    // Persistent state across the scan: c, d, mkv (mk*v folded).
    float c[EPT], d[EPT], mkv[EPT];
#pragma unroll
    for (int j = 0; j < EPT; ++j) {
        float m   = (t0 + j     < L) ? 1.f : 0.f;
        float mn  = (t0 + j + 1 < L) ? 1.f : 0.f;
        float nvj = ((j < EPT - 1) ? v[j + 1] : v_next) * mn;
        float delta = fmaf(GAMMA * nd[j], nvj, r[j]) - v[j];
        c[j]   = m * GL * nd[j];
        d[j]   = m * delta;
        mkv[j] = m * v[j];
    }

    // Thread-local composition over the 16 steps (reverse time order).
    float A = 1.f, Bc = 0.f;
#pragma unroll
    for (int j = EPT - 1; j >= 0; --j) {
        Bc = fmaf(c[j], Bc, d[j]);
        A  = c[j] * A;
    }

    // Warp-level inclusive suffix scan (Kogge-Stone, shfl_down).
    float a = A, b = Bc;
#pragma unroll
    for (int off = 1; off < 32; off <<= 1) {
        float ra = __shfl_down_sync(0xffffffffu, a, off);
        float rb = __shfl_down_sync(0xffffffffu, b, off);
        if (lane + off < 32) {
            b = fmaf(a, rb, b);
            a = a * ra;
        }
    }
    // Exclusive suffix within warp: E_i = inclusive(i+1); identity at lane 31.
    float ea = __shfl_down_sync(0xffffffffu, a, 1);
    float eb = __shfl_down_sync(0xffffffffu, b, 1);
    if (lane == 31) { ea = 1.f; eb = 0.f; }

    // Cross-warp scan over NW=4 warp aggregates.
    __shared__ float wa[NW];
    __shared__ float wb[NW];
    __shared__ float wcarry[NW];
    if (lane == 0) { wa[warp] = a; wb[warp] = b; }
    __syncthreads();
    if (warp == 0 && lane < NW) {
        float aa = wa[lane], bb = wb[lane];
#pragma unroll
        for (int off = 1; off < NW; off <<= 1) {
            float ra = __shfl_down_sync(0x0000000fu, aa, off);
            float rb = __shfl_down_sync(0x0000000fu, bb, off);
            if (lane + off < NW) {
                bb = fmaf(aa, rb, bb);
                aa = aa * ra;
            }
        }
        float carry = __shfl_down_sync(0x0000000fu, bb, 1);
        if (lane == NW - 1) carry = 0.f;
        wcarry[lane] = carry;
    }
    __syncthreads();

    // Carry entering this thread's chunk from the right, then final pass.
    float g = fmaf(ea, wcarry[warp], eb);

    float adv[EPT], ret[EPT];
#pragma unroll
    for (int j = EPT - 1; j >= 0; --j) {
        g = fmaf(c[j], g, d[j]);   // exactly 0 where invalid (c=d=0)
        adv[j] = g;
        ret[j] = g + mkv[j];
    }

    float4* ap = reinterpret_cast<float4*>(adv_out + base);
    float4* tp = reinterpret_cast<float4*>(ret_out + base);
#pragma unroll
    for (int i = 0; i < NSEG; ++i)
        __stcs(ap + i, make_float4(adv[4*i], adv[4*i+1], adv[4*i+2], adv[4*i+3]));
#pragma unroll
    for (int i = 0; i < NSEG; ++i)
        __stcs(tp + i, make_float4(ret[4*i], ret[4*i+1], ret[4*i+2], ret[4*i+3]));
}

extern "C" void kernel_launch(void* const* d_in, const int* in_sizes, int n_in,
                              void* d_out, int out_size)
{
    const float* rewards = (const float*)d_in[0];
    const float* values  = (const float*)d_in[1];
    const int*   dones   = (const int*)d_in[2];
    const int*   mask    = (const int*)d_in[3];

    const int total = in_sizes[0];            // B * S
    const int B     = total / S_LEN;

    float* adv_out = (float*)d_out;
    float* ret_out = (float*)d_out + (long long)B * S_LEN;

    // Kernel 1: exact per-row prefix lengths (one warp per row).
    const int lb = 256;
    const int lg = (B * 32 + lb - 1) / lb;
    len_kernel<<<lg, lb>>>(mask, B);

    // Kernel 2: streaming GAE scan; invalid-tail chunks skip input loads.
    gae_kernel<<<B, TPB>>>(rewards, values, dones, adv_out, ret_out);
}